// round 13
// baseline (speedup 1.0000x reference)
#include <cuda_runtime.h>
#include <cuda_fp16.h>
#include <cstdint>

// Problem:
//   x:      (B=4, T=4096, D=1024) f32
//   idx:    (B=4, E=8, C=1024)    i32
//   weight: (E=8, O=512, D=1024)  f32
//   bias:   (E=8, O=512)          f32
//   out:    (B=4, E=8, C=1024, O=512) f32
// out[b,e,c,o] = sum_d x[b, idx[b,e,c], d] * w[e,o,d] + bias[e,o]
//
// fp16 HMMA GEMM, fp32 accumulation (rel_err ~2.8e-4).
// mma.sync rt ceiling ~0.25 warp-MMA/cyc/SM; R8 main kernel was at 97%.
// This round: A (gathered x) converted fp32->fp16 IN-KERNEL (x is L2-resident),
// killing the 21us convert_x pre-pass. W stays preconverted (cheap, 5us).
// CTA 128x128, 8 warps (2Mx4N), warp tile 64x32, W 3-stage cp.async,
// single A smem buffer (blocking convert, 2 syncs/chunk), frag double-buffer,
// 2 CTAs/SM.

#define B_ 4
#define T_ 4096
#define D_ 1024
#define E_ 8
#define C_ 1024
#define O_ 512

#define MT 128
#define NT 128
#define KC 64             // fp16 k per chunk -> 128B rows
#define NCHUNK (D_ / KC)  // 16
#define WSTAGES 3
#define WSTAGE_SZ 16384   // W tile f16: 128 rows x 128B
#define A_SZ 16384        // A tile f16: 128 rows x 128B
#define SMEM_TOTAL (A_SZ + WSTAGES * WSTAGE_SZ)   // 65536

__device__ __half g_w16[E_ * O_ * D_];

#define NWG ((E_ * O_ * D_) / 8)

__device__ __forceinline__ uint32_t smem_u32(const void* p) {
    uint32_t a;
    asm("{ .reg .u64 t; cvta.to.shared.u64 t, %1; cvt.u32.u64 %0, t; }" : "=r"(a) : "l"(p));
    return a;
}
__device__ __forceinline__ void cp_async16(uint32_t dst, const void* src) {
    asm volatile("cp.async.cg.shared.global [%0], [%1], 16;" :: "r"(dst), "l"(src));
}
__device__ __forceinline__ void cp_commit() {
    asm volatile("cp.async.commit_group;" ::: "memory");
}
__device__ __forceinline__ void cp_wait1() {
    asm volatile("cp.async.wait_group 1;" ::: "memory");
}
__device__ __forceinline__ void ldsm_x4(uint32_t* r, uint32_t addr) {
    asm volatile("ldmatrix.sync.aligned.m8n8.x4.shared.b16 {%0,%1,%2,%3}, [%4];"
                 : "=r"(r[0]), "=r"(r[1]), "=r"(r[2]), "=r"(r[3]) : "r"(addr));
}
__device__ __forceinline__ void mma_fp16(float* c, const uint32_t* a, uint32_t b0, uint32_t b1) {
    asm volatile(
        "mma.sync.aligned.m16n8k16.row.col.f32.f16.f16.f32 "
        "{%0,%1,%2,%3}, {%4,%5,%6,%7}, {%8,%9}, {%0,%1,%2,%3};"
        : "+f"(c[0]), "+f"(c[1]), "+f"(c[2]), "+f"(c[3])
        : "r"(a[0]), "r"(a[1]), "r"(a[2]), "r"(a[3]), "r"(b0), "r"(b1));
}

// ---------------------------------------------------------------------------
// fp32 -> fp16 converter for w only
// ---------------------------------------------------------------------------
__global__ __launch_bounds__(256)
void convert_w_kernel(const float* __restrict__ w) {
    size_t i = ((size_t)blockIdx.x * 256 + threadIdx.x) * 8;
    float4 v0 = *(const float4*)(w + i);
    float4 v1 = *(const float4*)(w + i + 4);
    __half2 h0 = __floats2half2_rn(v0.x, v0.y);
    __half2 h1 = __floats2half2_rn(v0.z, v0.w);
    __half2 h2 = __floats2half2_rn(v1.x, v1.y);
    __half2 h3 = __floats2half2_rn(v1.z, v1.w);
    *reinterpret_cast<uint4*>(g_w16 + i) =
        make_uint4(*(uint32_t*)&h0, *(uint32_t*)&h1, *(uint32_t*)&h2, *(uint32_t*)&h3);
}

// ---------------------------------------------------------------------------
// Main GEMM: 256 threads, 8 warps 2(M)x4(N), warp tile 64x32
// ---------------------------------------------------------------------------
__global__ __launch_bounds__(256, 2)
void moe_fp16_kernel(const float* __restrict__ x,
                     const int*   __restrict__ idx,
                     const float* __restrict__ bias,
                     float*       __restrict__ out)
{
    extern __shared__ char smem[];
    const uint32_t sb = smem_u32(smem);
    const int tid  = threadIdx.x;
    const int wid  = tid >> 5;
    const int lane = tid & 31;

    const int be = blockIdx.z;
    const int b  = be >> 3;
    const int e  = be & 7;
    const int c0 = blockIdx.y * MT;
    const int o0 = blockIdx.x * NT;

    // ---- producer mapping: row = tid/2, 64B(f16) half = tid&1 ----
    const int prow  = tid >> 1;
    const int phalf = (tid & 1) * 64;     // byte offset within the 128B f16 row
    const int tok   = idx[be * C_ + c0 + prow];
    // A source: f32, this thread covers 32 floats (=128B f32 -> 64B f16)
    const float*  asrc = x + ((size_t)b * T_ + tok) * D_ + (size_t)(tid & 1) * 32;
    const __half* wsrc = g_w16 + ((size_t)(e * O_ + o0 + prow)) * D_ + (phalf >> 1);
    const uint32_t pXor  = (uint32_t)((prow & 7) << 4);
    const uint32_t pRowB = (uint32_t)(prow * 128);

    // ---- compute mapping ----
    const int wm = wid >> 2;                       // 0..1 -> M offset wm*64
    const int wn = wid & 3;                        // 0..3 -> N offset wn*32

    const uint32_t fXor = (uint32_t)((lane & 7) << 4);
    const uint32_t aBase = (uint32_t)((wm * 64 + (lane & 15)) * 128);          // in A buf
    const uint32_t aSegL = (uint32_t)((lane >> 4) * 16);
    const uint32_t wBase = (uint32_t)((wn * 32 + ((lane >> 4) << 3) + (lane & 7)) * 128);  // within a W stage
    const uint32_t wSegL = (uint32_t)(((lane >> 3) & 1) * 16);

    float acc[4][4][4];
    #pragma unroll
    for (int i = 0; i < 4; i++)
        #pragma unroll
        for (int j = 0; j < 4; j++)
            #pragma unroll
            for (int q = 0; q < 4; q++) acc[i][j][q] = 0.0f;

    // W stage loader (cp.async, 4x16B per thread)
    auto load_w_stage = [&](int st, int kc) {
        const uint32_t wbase = sb + A_SZ + st * WSTAGE_SZ + pRowB;
        const __half* wp = wsrc + kc * KC;
        #pragma unroll
        for (int j = 0; j < 4; j++) {
            const uint32_t off = ((uint32_t)(phalf + j * 16)) ^ pXor;
            cp_async16(wbase + off, wp + j * 8);
        }
    };

    load_w_stage(0, 0); cp_commit();
    load_w_stage(1, 1); cp_commit();

    uint32_t af[2][4][4];   // [buf][mt][frag]
    uint32_t wf[2][2][4];   // [buf][np][frag]

    const uint32_t aSmemBase = sb + pRowB;   // A STS base for this thread

    for (int kc = 0; kc < NCHUNK; kc++) {
        cp_wait1();
        __syncthreads();   // A buffer free (chunk kc-1 consumed), W(kc) resident

        // ---- A: LDG f32 -> cvt f16 -> STS (blocking, single buffer) ----
        float4 av[8];
        const float* ap = asrc + kc * KC;   // KC f16 cols == KC f32 elems span? NO:
        // careful: thread covers f32 elems [ (tid&1)*32 , +32 ) of the 64-col chunk
        // chunk kc covers f32 cols [kc*64, kc*64+64)
        #pragma unroll
        for (int j = 0; j < 8; j++)
            av[j] = *(const float4*)(x + ((size_t)b * T_ + tok) * D_ + kc * KC + (tid & 1) * 32 + 4 * j);

        if (kc + 2 < NCHUNK) load_w_stage((kc + 2) % WSTAGES, kc + 2);
        cp_commit();   // empty groups at tail keep wait_group counts valid

        #pragma unroll
        for (int j = 0; j < 4; j++) {
            __half2 h0 = __floats2half2_rn(av[2 * j].x, av[2 * j].y);
            __half2 h1 = __floats2half2_rn(av[2 * j].z, av[2 * j].w);
            __half2 h2 = __floats2half2_rn(av[2 * j + 1].x, av[2 * j + 1].y);
            __half2 h3 = __floats2half2_rn(av[2 * j + 1].z, av[2 * j + 1].w);
            const uint32_t off = ((uint32_t)(phalf + j * 16)) ^ pXor;
            *reinterpret_cast<uint4*>(smem + (pRowB + off)) =
                make_uint4(*(uint32_t*)&h0, *(uint32_t*)&h1, *(uint32_t*)&h2, *(uint32_t*)&h3);
        }
        __syncthreads();   // A(kc) visible

        const uint32_t aAddr = sb + aBase;
        const uint32_t wAddr = sb + A_SZ + (kc % WSTAGES) * WSTAGE_SZ + wBase;

        // preload ks=0 fragments
        #pragma unroll
        for (int mt = 0; mt < 4; mt++)
            ldsm_x4(af[0][mt], aAddr + mt * 2048 + ((0 + aSegL) ^ fXor));
        #pragma unroll
        for (int np = 0; np < 2; np++)
            ldsm_x4(wf[0][np], wAddr + np * 2048 + ((0 + wSegL) ^ fXor));

        #pragma unroll
        for (int ks = 0; ks < 4; ks++) {
            const int cur = ks & 1;
            const int nxt = cur ^ 1;
            if (ks < 3) {
                const uint32_t kb = (uint32_t)((ks + 1) * 32);
                #pragma unroll
                for (int mt = 0; mt < 4; mt++)
                    ldsm_x4(af[nxt][mt], aAddr + mt * 2048 + ((kb + aSegL) ^ fXor));
                #pragma unroll
                for (int np = 0; np < 2; np++)
                    ldsm_x4(wf[nxt][np], wAddr + np * 2048 + ((kb + wSegL) ^ fXor));
            }
            #pragma unroll
            for (int mt = 0; mt < 4; mt++)
                #pragma unroll
                for (int np = 0; np < 2; np++) {
                    mma_fp16(acc[mt][np * 2 + 0], af[cur][mt], wf[cur][np][0], wf[cur][np][1]);
                    mma_fp16(acc[mt][np * 2 + 1], af[cur][mt], wf[cur][np][2], wf[cur][np][3]);
                }
        }
    }

    // ---- epilogue ----
    float2 bv[4];
    #pragma unroll
    for (int n4 = 0; n4 < 4; n4++)
        bv[n4] = *reinterpret_cast<const float2*>(bias + e * O_ + o0 + wn * 32 + n4 * 8 + (lane & 3) * 2);

    #pragma unroll
    for (int mt = 0; mt < 4; mt++) {
        const int row = wm * 64 + mt * 16 + (lane >> 2);
        float* d0 = out + ((size_t)be * C_ + c0 + row) * O_ + o0;
        float* d1 = d0 + 8 * O_;
        #pragma unroll
        for (int n4 = 0; n4 < 4; n4++) {
            const int col = wn * 32 + n4 * 8 + (lane & 3) * 2;
            float2 v0, v1;
            v0.x = acc[mt][n4][0] + bv[n4].x;
            v0.y = acc[mt][n4][1] + bv[n4].y;
            v1.x = acc[mt][n4][2] + bv[n4].x;
            v1.y = acc[mt][n4][3] + bv[n4].y;
            *reinterpret_cast<float2*>(d0 + col) = v0;
            *reinterpret_cast<float2*>(d1 + col) = v1;
        }
    }
}

extern "C" void kernel_launch(void* const* d_in, const int* in_sizes, int n_in,
                              void* d_out, int out_size)
{
    const float* x    = (const float*)d_in[0];
    const int*   idx  = (const int*)  d_in[1];
    const float* w    = (const float*)d_in[2];
    const float* bias = (const float*)d_in[3];
    float* out = (float*)d_out;

    cudaFuncSetAttribute(moe_fp16_kernel,
                         cudaFuncAttributeMaxDynamicSharedMemorySize, SMEM_TOTAL);

    convert_w_kernel<<<NWG / 256, 256>>>(w);

    dim3 grid(O_ / NT, C_ / MT, B_ * E_);   // (4, 8, 32)
    moe_fp16_kernel<<<grid, 256, SMEM_TOTAL>>>(x, idx, bias, out);
}

// round 14
// speedup vs baseline: 1.2402x; 1.2402x over previous
#include <cuda_runtime.h>
#include <cuda_fp16.h>
#include <cstdint>

// Problem:
//   x:      (B=4, T=4096, D=1024) f32
//   idx:    (B=4, E=8, C=1024)    i32
//   weight: (E=8, O=512, D=1024)  f32
//   bias:   (E=8, O=512)          f32
//   out:    (B=4, E=8, C=1024, O=512) f32
// out[b,e,c,o] = sum_d x[b, idx[b,e,c], d] * w[e,o,d] + bias[e,o]
//
// fp16 HMMA GEMM, fp32 accumulation (rel_err ~2.8e-4).
// - W preconverted to f16 (cheap pre-pass), 3-stage cp.async.
// - A (gathered x) converted f32->f16 IN-KERNEL, non-blocking: next chunk's
//   f32 loaded to registers DURING current MMA phase, STS'd after barrier.
// - Tile 64(M) x 128(N) -> 2048 CTAs: 6.92 waves @296 slots, ~1% tail
//   (vs 15% at 1024 tiles).
// 8 warps (2M x 4N), warp tile 32x32, frag double-buffer, 2 CTAs/SM.

#define B_ 4
#define T_ 4096
#define D_ 1024
#define E_ 8
#define C_ 1024
#define O_ 512

#define MT 64
#define NT 128
#define KC 64             // f16 k per chunk -> 128B rows
#define NCHUNK (D_ / KC)  // 16
#define WSTAGES 3
#define A_SZ 8192                   // 64 rows x 128B
#define WSTAGE_SZ 16384             // 128 rows x 128B
#define SMEM_TOTAL (A_SZ + WSTAGES * WSTAGE_SZ)   // 57344

__device__ __half g_w16[E_ * O_ * D_];
#define NWG ((E_ * O_ * D_) / 8)

__device__ __forceinline__ uint32_t smem_u32(const void* p) {
    uint32_t a;
    asm("{ .reg .u64 t; cvta.to.shared.u64 t, %1; cvt.u32.u64 %0, t; }" : "=r"(a) : "l"(p));
    return a;
}
__device__ __forceinline__ void cp_async16(uint32_t dst, const void* src) {
    asm volatile("cp.async.cg.shared.global [%0], [%1], 16;" :: "r"(dst), "l"(src));
}
__device__ __forceinline__ void cp_commit() {
    asm volatile("cp.async.commit_group;" ::: "memory");
}
__device__ __forceinline__ void cp_wait1() {
    asm volatile("cp.async.wait_group 1;" ::: "memory");
}
__device__ __forceinline__ void ldsm_x4(uint32_t* r, uint32_t addr) {
    asm volatile("ldmatrix.sync.aligned.m8n8.x4.shared.b16 {%0,%1,%2,%3}, [%4];"
                 : "=r"(r[0]), "=r"(r[1]), "=r"(r[2]), "=r"(r[3]) : "r"(addr));
}
__device__ __forceinline__ void mma_fp16(float* c, const uint32_t* a, uint32_t b0, uint32_t b1) {
    asm volatile(
        "mma.sync.aligned.m16n8k16.row.col.f32.f16.f16.f32 "
        "{%0,%1,%2,%3}, {%4,%5,%6,%7}, {%8,%9}, {%0,%1,%2,%3};"
        : "+f"(c[0]), "+f"(c[1]), "+f"(c[2]), "+f"(c[3])
        : "r"(a[0]), "r"(a[1]), "r"(a[2]), "r"(a[3]), "r"(b0), "r"(b1));
}

// ---------------------------------------------------------------------------
// fp32 -> fp16 converter for w only
// ---------------------------------------------------------------------------
__global__ __launch_bounds__(256)
void convert_w_kernel(const float* __restrict__ w) {
    size_t i = ((size_t)blockIdx.x * 256 + threadIdx.x) * 8;
    float4 v0 = *(const float4*)(w + i);
    float4 v1 = *(const float4*)(w + i + 4);
    __half2 h0 = __floats2half2_rn(v0.x, v0.y);
    __half2 h1 = __floats2half2_rn(v0.z, v0.w);
    __half2 h2 = __floats2half2_rn(v1.x, v1.y);
    __half2 h3 = __floats2half2_rn(v1.z, v1.w);
    *reinterpret_cast<uint4*>(g_w16 + i) =
        make_uint4(*(uint32_t*)&h0, *(uint32_t*)&h1, *(uint32_t*)&h2, *(uint32_t*)&h3);
}

// ---------------------------------------------------------------------------
// Main GEMM: 256 threads, 8 warps 2(M)x4(N), warp tile 32x32
// ---------------------------------------------------------------------------
__global__ __launch_bounds__(256, 2)
void moe_fp16_kernel(const float* __restrict__ x,
                     const int*   __restrict__ idx,
                     const float* __restrict__ bias,
                     float*       __restrict__ out)
{
    extern __shared__ char smem[];
    const uint32_t sb = smem_u32(smem);
    const int tid  = threadIdx.x;
    const int wid  = tid >> 5;
    const int lane = tid & 31;

    const int be = blockIdx.z;
    const int b  = be >> 3;
    const int e  = be & 7;
    const int c0 = blockIdx.y * MT;
    const int o0 = blockIdx.x * NT;

    // ---- A producer: row = tid/4 (0..63), quarter q = tid&3 (32B f16 / 16 f32) ----
    const int arow = tid >> 2;
    const int aq   = tid & 3;
    const int tok  = idx[be * C_ + c0 + arow];
    const float* asrc = x + ((size_t)b * T_ + tok) * D_ + aq * 16;
    const uint32_t aXorP = (uint32_t)((arow & 7) << 4);
    const uint32_t aRowP = (uint32_t)(arow * 128);

    // ---- W producer: row = tid/2 (0..127), half = tid&1 (64B) ----
    const int prow  = tid >> 1;
    const int phalf = (tid & 1) * 64;
    const __half* wsrc = g_w16 + ((size_t)(e * O_ + o0 + prow)) * D_ + (phalf >> 1);
    const uint32_t pXor  = (uint32_t)((prow & 7) << 4);
    const uint32_t pRowB = (uint32_t)(prow * 128);

    // ---- compute mapping: warp (wm, wn) owns 32x32 ----
    const int wm = wid >> 2;                       // 0..1 -> M offset wm*32
    const int wn = wid & 3;                        // 0..3 -> N offset wn*32

    const uint32_t fXor = (uint32_t)((lane & 7) << 4);
    const uint32_t aBase = (uint32_t)((wm * 32 + (lane & 15)) * 128);
    const uint32_t aSegL = (uint32_t)((lane >> 4) * 16);
    const uint32_t wBase = (uint32_t)(A_SZ + (wn * 32 + ((lane >> 4) << 3) + (lane & 7)) * 128);
    const uint32_t wSegL = (uint32_t)(((lane >> 3) & 1) * 16);

    float acc[2][4][4];
    #pragma unroll
    for (int i = 0; i < 2; i++)
        #pragma unroll
        for (int j = 0; j < 4; j++)
            #pragma unroll
            for (int q = 0; q < 4; q++) acc[i][j][q] = 0.0f;

    auto load_w_stage = [&](int st, int kc) {
        const uint32_t wbase = sb + A_SZ + st * WSTAGE_SZ + pRowB;
        const __half* wp = wsrc + kc * KC;
        #pragma unroll
        for (int j = 0; j < 4; j++) {
            const uint32_t off = ((uint32_t)(phalf + j * 16)) ^ pXor;
            cp_async16(wbase + off, wp + j * 8);
        }
    };

    // prologue: W0, W1 in flight; A(0) f32 in registers
    load_w_stage(0, 0); cp_commit();
    load_w_stage(1, 1); cp_commit();

    float4 areg[4];
    #pragma unroll
    for (int j = 0; j < 4; j++) areg[j] = *(const float4*)(asrc + 4 * j);

    uint32_t af[2][2][4];   // [buf][mt][frag]
    uint32_t wf[2][2][4];   // [buf][np][frag]

    for (int kc = 0; kc < NCHUNK; kc++) {
        cp_wait1();          // W(kc) resident
        __syncthreads();     // A buffer free (MMA of kc-1 finished reading)

        // ---- STS A(kc): convert the prefetched f32 registers ----
        {
            __half2 h0 = __floats2half2_rn(areg[0].x, areg[0].y);
            __half2 h1 = __floats2half2_rn(areg[0].z, areg[0].w);
            __half2 h2 = __floats2half2_rn(areg[1].x, areg[1].y);
            __half2 h3 = __floats2half2_rn(areg[1].z, areg[1].w);
            __half2 h4 = __floats2half2_rn(areg[2].x, areg[2].y);
            __half2 h5 = __floats2half2_rn(areg[2].z, areg[2].w);
            __half2 h6 = __floats2half2_rn(areg[3].x, areg[3].y);
            __half2 h7 = __floats2half2_rn(areg[3].z, areg[3].w);
            const uint32_t o0b = ((uint32_t)(aq * 32)) ^ aXorP;
            const uint32_t o1b = ((uint32_t)(aq * 32 + 16)) ^ aXorP;
            *reinterpret_cast<uint4*>(smem + aRowP + o0b) =
                make_uint4(*(uint32_t*)&h0, *(uint32_t*)&h1, *(uint32_t*)&h2, *(uint32_t*)&h3);
            *reinterpret_cast<uint4*>(smem + aRowP + o1b) =
                make_uint4(*(uint32_t*)&h4, *(uint32_t*)&h5, *(uint32_t*)&h6, *(uint32_t*)&h7);
        }
        __syncthreads();     // A(kc) visible

        // ---- async prefetches for later chunks (overlap with MMA below) ----
        if (kc + 2 < NCHUNK) load_w_stage((kc + 2) % WSTAGES, kc + 2);
        cp_commit();         // empty groups at tail keep wait_group counts valid
        if (kc + 1 < NCHUNK) {
            const float* ap = asrc + (kc + 1) * KC;
            #pragma unroll
            for (int j = 0; j < 4; j++) areg[j] = *(const float4*)(ap + 4 * j);
        }

        const uint32_t aAddr = sb + aBase;
        const uint32_t wAddr = sb + (uint32_t)((kc % WSTAGES) * WSTAGE_SZ) + wBase;

        // preload ks=0 fragments
        #pragma unroll
        for (int mt = 0; mt < 2; mt++)
            ldsm_x4(af[0][mt], aAddr + mt * 2048 + ((0 + aSegL) ^ fXor));
        #pragma unroll
        for (int np = 0; np < 2; np++)
            ldsm_x4(wf[0][np], wAddr + np * 2048 + ((0 + wSegL) ^ fXor));

        #pragma unroll
        for (int ks = 0; ks < 4; ks++) {
            const int cur = ks & 1;
            const int nxt = cur ^ 1;
            if (ks < 3) {
                const uint32_t kb = (uint32_t)((ks + 1) * 32);
                #pragma unroll
                for (int mt = 0; mt < 2; mt++)
                    ldsm_x4(af[nxt][mt], aAddr + mt * 2048 + ((kb + aSegL) ^ fXor));
                #pragma unroll
                for (int np = 0; np < 2; np++)
                    ldsm_x4(wf[nxt][np], wAddr + np * 2048 + ((kb + wSegL) ^ fXor));
            }
            #pragma unroll
            for (int mt = 0; mt < 2; mt++)
                #pragma unroll
                for (int np = 0; np < 2; np++) {
                    mma_fp16(acc[mt][np * 2 + 0], af[cur][mt], wf[cur][np][0], wf[cur][np][1]);
                    mma_fp16(acc[mt][np * 2 + 1], af[cur][mt], wf[cur][np][2], wf[cur][np][3]);
                }
        }
    }

    // ---- epilogue ----
    float2 bv[4];
    #pragma unroll
    for (int n4 = 0; n4 < 4; n4++)
        bv[n4] = *reinterpret_cast<const float2*>(bias + e * O_ + o0 + wn * 32 + n4 * 8 + (lane & 3) * 2);

    #pragma unroll
    for (int mt = 0; mt < 2; mt++) {
        const int row = wm * 32 + mt * 16 + (lane >> 2);
        float* d0 = out + ((size_t)be * C_ + c0 + row) * O_ + o0;
        float* d1 = d0 + 8 * O_;
        #pragma unroll
        for (int n4 = 0; n4 < 4; n4++) {
            const int col = wn * 32 + n4 * 8 + (lane & 3) * 2;
            float2 v0, v1;
            v0.x = acc[mt][n4][0] + bv[n4].x;
            v0.y = acc[mt][n4][1] + bv[n4].y;
            v1.x = acc[mt][n4][2] + bv[n4].x;
            v1.y = acc[mt][n4][3] + bv[n4].y;
            *reinterpret_cast<float2*>(d0 + col) = v0;
            *reinterpret_cast<float2*>(d1 + col) = v1;
        }
    }
}

extern "C" void kernel_launch(void* const* d_in, const int* in_sizes, int n_in,
                              void* d_out, int out_size)
{
    const float* x    = (const float*)d_in[0];
    const int*   idx  = (const int*)  d_in[1];
    const float* w    = (const float*)d_in[2];
    const float* bias = (const float*)d_in[3];
    float* out = (float*)d_out;

    cudaFuncSetAttribute(moe_fp16_kernel,
                         cudaFuncAttributeMaxDynamicSharedMemorySize, SMEM_TOTAL);

    convert_w_kernel<<<NWG / 256, 256>>>(w);

    dim3 grid(O_ / NT, C_ / MT, B_ * E_);   // (4, 16, 32) = 2048 CTAs
    moe_fp16_kernel<<<grid, 256, SMEM_TOTAL>>>(x, idx, bias, out);
}

// round 15
// speedup vs baseline: 1.2949x; 1.0441x over previous
#include <cuda_runtime.h>
#include <cuda_fp16.h>
#include <cstdint>

// Problem:
//   x:      (B=4, T=4096, D=1024) f32
//   idx:    (B=4, E=8, C=1024)    i32
//   weight: (E=8, O=512, D=1024)  f32
//   bias:   (E=8, O=512)          f32
//   out:    (B=4, E=8, C=1024, O=512) f32
// out[b,e,c,o] = sum_d x[b, idx[b,e,c], d] * w[e,o,d] + bias[e,o]
//
// fp16 HMMA GEMM, fp32 accumulation (rel_err ~2.8e-4).
// R8 skeleton (CTA 128x128, 8 warps 2Mx4N, warp tile 64x32, frag double
// buffer, 2 CTAs/SM) at ~97% of the mma.sync ceiling. This round removes the
// convert_x DRAM round trip: gathered A rows are cp.async'd as f32 into a
// smem staging buffer, converted f32->f16 smem-to-smem in the producer phase
// (each thread touches only its own bytes -> no extra hazards). W stays
// preconverted f16 with a 2-stage cp.async pipeline.

#define B_ 4
#define T_ 4096
#define D_ 1024
#define E_ 8
#define C_ 1024
#define O_ 512

#define MT 128
#define NT 128
#define KC 64             // f16 k per chunk -> 128B f16 rows, 256B f32 rows
#define NCHUNK (D_ / KC)  // 16

#define A32_OFF 0                 // f32 staging: 128 rows x 256B = 32768
#define A16_OFF 32768             // f16 A tile:  128 rows x 128B = 16384
#define W_OFF   49152             // W f16: 2 stages x 16384
#define WSTAGE_SZ 16384
#define SMEM_TOTAL 81920          // x2 CTAs = 160KB <= 228KB

__device__ __half g_w16[E_ * O_ * D_];
#define NWG ((E_ * O_ * D_) / 8)

__device__ __forceinline__ uint32_t smem_u32(const void* p) {
    uint32_t a;
    asm("{ .reg .u64 t; cvta.to.shared.u64 t, %1; cvt.u32.u64 %0, t; }" : "=r"(a) : "l"(p));
    return a;
}
__device__ __forceinline__ void cp_async16(uint32_t dst, const void* src) {
    asm volatile("cp.async.cg.shared.global [%0], [%1], 16;" :: "r"(dst), "l"(src));
}
__device__ __forceinline__ void cp_commit() {
    asm volatile("cp.async.commit_group;" ::: "memory");
}
__device__ __forceinline__ void cp_wait0() {
    asm volatile("cp.async.wait_group 0;" ::: "memory");
}
__device__ __forceinline__ void ldsm_x4(uint32_t* r, uint32_t addr) {
    asm volatile("ldmatrix.sync.aligned.m8n8.x4.shared.b16 {%0,%1,%2,%3}, [%4];"
                 : "=r"(r[0]), "=r"(r[1]), "=r"(r[2]), "=r"(r[3]) : "r"(addr));
}
__device__ __forceinline__ void mma_fp16(float* c, const uint32_t* a, uint32_t b0, uint32_t b1) {
    asm volatile(
        "mma.sync.aligned.m16n8k16.row.col.f32.f16.f16.f32 "
        "{%0,%1,%2,%3}, {%4,%5,%6,%7}, {%8,%9}, {%0,%1,%2,%3};"
        : "+f"(c[0]), "+f"(c[1]), "+f"(c[2]), "+f"(c[3])
        : "r"(a[0]), "r"(a[1]), "r"(a[2]), "r"(a[3]), "r"(b0), "r"(b1));
}

// ---------------------------------------------------------------------------
// fp32 -> fp16 converter for w only (24MB traffic, ~5us)
// ---------------------------------------------------------------------------
__global__ __launch_bounds__(256)
void convert_w_kernel(const float* __restrict__ w) {
    size_t i = ((size_t)blockIdx.x * 256 + threadIdx.x) * 8;
    float4 v0 = *(const float4*)(w + i);
    float4 v1 = *(const float4*)(w + i + 4);
    __half2 h0 = __floats2half2_rn(v0.x, v0.y);
    __half2 h1 = __floats2half2_rn(v0.z, v0.w);
    __half2 h2 = __floats2half2_rn(v1.x, v1.y);
    __half2 h3 = __floats2half2_rn(v1.z, v1.w);
    *reinterpret_cast<uint4*>(g_w16 + i) =
        make_uint4(*(uint32_t*)&h0, *(uint32_t*)&h1, *(uint32_t*)&h2, *(uint32_t*)&h3);
}

// ---------------------------------------------------------------------------
// Main GEMM: 256 threads, 8 warps 2(M)x4(N), warp tile 64x32
// ---------------------------------------------------------------------------
__global__ __launch_bounds__(256, 2)
void moe_fp16_kernel(const float* __restrict__ x,
                     const int*   __restrict__ idx,
                     const float* __restrict__ bias,
                     float*       __restrict__ out)
{
    extern __shared__ char smem[];
    const uint32_t sb = smem_u32(smem);
    const int tid  = threadIdx.x;
    const int wid  = tid >> 5;
    const int lane = tid & 31;

    const int be = blockIdx.z;
    const int b  = be >> 3;
    const int e  = be & 7;
    const int c0 = blockIdx.y * MT;
    const int o0 = blockIdx.x * NT;

    // ---- A producer: row = tid/2 (0..127), half h = tid&1 ----
    // Thread owns 8 interleaved 16B f32 units u = 2j+h (j=0..7) of its row's
    // 64-f32 chunk. A32 staging layout: row*256 + (u ^ ((row&7)<<1))*16.
    const int arow = tid >> 1;
    const int ah   = tid & 1;
    const int tok  = idx[be * C_ + c0 + arow];
    const float* xrow = x + ((size_t)b * T_ + tok) * D_;
    const uint32_t a32row = (uint32_t)(A32_OFF + arow * 256);
    const uint32_t a32sw  = (uint32_t)((arow & 7) << 1);   // xor on 16B-unit index
    const uint32_t a16sw  = (uint32_t)((arow & 7) << 4);   // xor on byte offset
    const uint32_t a16row = (uint32_t)(A16_OFF + arow * 128);

    // ---- W producer: row = tid/2, 64B half ----
    const int prow  = tid >> 1;
    const int phalf = (tid & 1) * 64;
    const __half* wsrc = g_w16 + ((size_t)(e * O_ + o0 + prow)) * D_ + (phalf >> 1);
    const uint32_t pXor  = (uint32_t)((prow & 7) << 4);
    const uint32_t pRowB = (uint32_t)(prow * 128);

    // ---- compute mapping (R8) ----
    const int wm = wid >> 2;
    const int wn = wid & 3;
    const uint32_t fXor = (uint32_t)((lane & 7) << 4);
    const uint32_t aBase = (uint32_t)(A16_OFF + (wm * 64 + (lane & 15)) * 128);
    const uint32_t aSegL = (uint32_t)((lane >> 4) * 16);
    const uint32_t wBase = (uint32_t)((wn * 32 + ((lane >> 4) << 3) + (lane & 7)) * 128);
    const uint32_t wSegL = (uint32_t)(((lane >> 3) & 1) * 16);

    float acc[4][4][4];
    #pragma unroll
    for (int i = 0; i < 4; i++)
        #pragma unroll
        for (int j = 0; j < 4; j++)
            #pragma unroll
            for (int q = 0; q < 4; q++) acc[i][j][q] = 0.0f;

    auto load_a32 = [&](int kc) {
        const float* src = xrow + kc * KC;
        #pragma unroll
        for (int j = 0; j < 8; j++) {
            const uint32_t u = (uint32_t)(2 * j + ah);
            cp_async16(sb + a32row + ((u ^ a32sw) << 4), src + u * 4);
        }
    };
    auto load_w = [&](int kc) {
        const uint32_t wbase = sb + W_OFF + (uint32_t)((kc & 1) * WSTAGE_SZ) + pRowB;
        const __half* wp = wsrc + kc * KC;
        #pragma unroll
        for (int j = 0; j < 4; j++) {
            const uint32_t off = ((uint32_t)(phalf + j * 16)) ^ pXor;
            cp_async16(wbase + off, wp + j * 8);
        }
    };

    // prologue: W(0), A32(0) in flight
    load_w(0);
    load_a32(0);
    cp_commit();

    uint32_t af[2][4][4];
    uint32_t wf[2][2][4];

    for (int kc = 0; kc < NCHUNK; kc++) {
        cp_wait0();          // W(kc), A32(kc) resident (only outstanding groups)
        __syncthreads();     // prev MMA done: A16 free, other W buffer free

        // W(kc+1) into the other stage (freed by MMA(kc-1))
        if (kc + 1 < NCHUNK) load_w(kc + 1);

        // ---- convert A32(kc) -> A16 (thread touches only its own bytes) ----
        #pragma unroll
        for (int j = 0; j < 8; j++) {
            const uint32_t u = (uint32_t)(2 * j + ah);
            const float4 v = *reinterpret_cast<const float4*>(
                smem + a32row + ((u ^ a32sw) << 4));
            __half2 h0 = __floats2half2_rn(v.x, v.y);
            __half2 h1 = __floats2half2_rn(v.z, v.w);
            // logical f16 bytes [8u, 8u+8); swizzle on 16B units
            const uint32_t off = ((uint32_t)(u * 8)) ^ a16sw;
            *reinterpret_cast<uint2*>(smem + a16row + off) =
                make_uint2(*(uint32_t*)&h0, *(uint32_t*)&h1);
        }

        // A32(kc+1): safe, this thread just finished reading its own bytes
        if (kc + 1 < NCHUNK) load_a32(kc + 1);
        cp_commit();

        __syncthreads();     // A16(kc) visible to all warps

        const uint32_t aAddr = sb + aBase;
        const uint32_t wAddr = sb + W_OFF + (uint32_t)((kc & 1) * WSTAGE_SZ) + wBase;

        // preload ks=0 fragments
        #pragma unroll
        for (int mt = 0; mt < 4; mt++)
            ldsm_x4(af[0][mt], aAddr + mt * 2048 + ((0 + aSegL) ^ fXor));
        #pragma unroll
        for (int np = 0; np < 2; np++)
            ldsm_x4(wf[0][np], wAddr + np * 2048 + ((0 + wSegL) ^ fXor));

        #pragma unroll
        for (int ks = 0; ks < 4; ks++) {
            const int cur = ks & 1;
            const int nxt = cur ^ 1;
            if (ks < 3) {
                const uint32_t kb = (uint32_t)((ks + 1) * 32);
                #pragma unroll
                for (int mt = 0; mt < 4; mt++)
                    ldsm_x4(af[nxt][mt], aAddr + mt * 2048 + ((kb + aSegL) ^ fXor));
                #pragma unroll
                for (int np = 0; np < 2; np++)
                    ldsm_x4(wf[nxt][np], wAddr + np * 2048 + ((kb + wSegL) ^ fXor));
            }
            #pragma unroll
            for (int mt = 0; mt < 4; mt++)
                #pragma unroll
                for (int np = 0; np < 2; np++) {
                    mma_fp16(acc[mt][np * 2 + 0], af[cur][mt], wf[cur][np][0], wf[cur][np][1]);
                    mma_fp16(acc[mt][np * 2 + 1], af[cur][mt], wf[cur][np][2], wf[cur][np][3]);
                }
        }
    }

    // ---- epilogue ----
    float2 bv[4];
    #pragma unroll
    for (int n4 = 0; n4 < 4; n4++)
        bv[n4] = *reinterpret_cast<const float2*>(bias + e * O_ + o0 + wn * 32 + n4 * 8 + (lane & 3) * 2);

    #pragma unroll
    for (int mt = 0; mt < 4; mt++) {
        const int row = wm * 64 + mt * 16 + (lane >> 2);
        float* d0 = out + ((size_t)be * C_ + c0 + row) * O_ + o0;
        float* d1 = d0 + 8 * O_;
        #pragma unroll
        for (int n4 = 0; n4 < 4; n4++) {
            const int col = wn * 32 + n4 * 8 + (lane & 3) * 2;
            float2 v0, v1;
            v0.x = acc[mt][n4][0] + bv[n4].x;
            v0.y = acc[mt][n4][1] + bv[n4].y;
            v1.x = acc[mt][n4][2] + bv[n4].x;
            v1.y = acc[mt][n4][3] + bv[n4].y;
            *reinterpret_cast<float2*>(d0 + col) = v0;
            *reinterpret_cast<float2*>(d1 + col) = v1;
        }
    }
}

extern "C" void kernel_launch(void* const* d_in, const int* in_sizes, int n_in,
                              void* d_out, int out_size)
{
    const float* x    = (const float*)d_in[0];
    const int*   idx  = (const int*)  d_in[1];
    const float* w    = (const float*)d_in[2];
    const float* bias = (const float*)d_in[3];
    float* out = (float*)d_out;

    cudaFuncSetAttribute(moe_fp16_kernel,
                         cudaFuncAttributeMaxDynamicSharedMemorySize, SMEM_TOTAL);

    convert_w_kernel<<<NWG / 256, 256>>>(w);

    dim3 grid(O_ / NT, C_ / MT, B_ * E_);   // (4, 8, 32)
    moe_fp16_kernel<<<grid, 256, SMEM_TOTAL>>>(x, idx, bias, out);
}